// round 3
// baseline (speedup 1.0000x reference)
#include <cuda_runtime.h>
#include <math.h>

// Problem constants (fixed by the dataset)
#define NMAX   100000
#define DIMC   128
#define HID    512
#define KTAPS  343

// ---------------- scratch (device globals; no allocation allowed) ----------
__device__ float g_x1[(size_t)NMAX * DIMC];   // post dwconv+LN        (51.2 MB)
__device__ float g_h [(size_t)NMAX * HID];    // post pwconv1+GELU     (204.8 MB)
__device__ float g_ssq[HID];                  // per-channel sum of squares
__device__ float g_s  [HID];                  // GRN row scale: grn_g*nx + 1
__device__ float g_w2p[HID * DIMC];           // diag(s) @ w2
__device__ float g_b2p[DIMC];                 // grn_b @ w2 + b2

// ---------------------------------------------------------------------------
__global__ void zero_ssq_k() { g_ssq[threadIdx.x] = 0.f; }

// ---------------- Kernel A: sparse depthwise conv + LayerNorm --------------
// One warp per site. Lane l owns channels [4l, 4l+3] (float4).
// Sentinel (idx==n) taps are skipped via ballot — only ~9/343 are valid.
__global__ __launch_bounds__(256) void dwconv_ln_k(
    const float* __restrict__ feats, const int* __restrict__ nbr,
    const float* __restrict__ dw_w, const float* __restrict__ dw_b,
    const float* __restrict__ ln_g, const float* __restrict__ ln_b, int n)
{
    int site = (blockIdx.x * blockDim.x + threadIdx.x) >> 5;
    int lane = threadIdx.x & 31;
    if (site >= n) return;

    const int* row = nbr + (size_t)site * KTAPS;
    float4 acc = make_float4(0.f, 0.f, 0.f, 0.f);

    for (int k0 = 0; k0 < KTAPS; k0 += 32) {
        int k   = k0 + lane;
        int idx = (k < KTAPS) ? row[k] : n;          // sentinel if out of range
        unsigned valid = __ballot_sync(0xffffffffu, idx < n);
        while (valid) {
            int b = __ffs(valid) - 1;
            valid &= valid - 1;
            int j  = __shfl_sync(0xffffffffu, idx, b);
            int kk = k0 + b;
            float4 f = *(const float4*)(feats + (size_t)j * DIMC + lane * 4);
            float4 w = *(const float4*)(dw_w + kk * DIMC + lane * 4);
            acc.x = fmaf(f.x, w.x, acc.x);
            acc.y = fmaf(f.y, w.y, acc.y);
            acc.z = fmaf(f.z, w.z, acc.z);
            acc.w = fmaf(f.w, w.w, acc.w);
        }
    }
    float4 bb = *(const float4*)(dw_b + lane * 4);
    acc.x += bb.x; acc.y += bb.y; acc.z += bb.z; acc.w += bb.w;

    // LayerNorm over 128 channels (warp reduce of sum & sumsq)
    float s1 = acc.x + acc.y + acc.z + acc.w;
    float s2 = acc.x*acc.x + acc.y*acc.y + acc.z*acc.z + acc.w*acc.w;
    #pragma unroll
    for (int o = 16; o; o >>= 1) {
        s1 += __shfl_xor_sync(0xffffffffu, s1, o);
        s2 += __shfl_xor_sync(0xffffffffu, s2, o);
    }
    float mean = s1 * (1.f / DIMC);
    float var  = s2 * (1.f / DIMC) - mean * mean;
    float rstd = rsqrtf(var + 1e-6f);

    float4 g = *(const float4*)(ln_g + lane * 4);
    float4 b = *(const float4*)(ln_b + lane * 4);
    float4 o4;
    o4.x = (acc.x - mean) * rstd * g.x + b.x;
    o4.y = (acc.y - mean) * rstd * g.y + b.y;
    o4.z = (acc.z - mean) * rstd * g.z + b.z;
    o4.w = (acc.w - mean) * rstd * g.w + b.w;
    *(float4*)(g_x1 + (size_t)site * DIMC + lane * 4) = o4;
}

// ---------------- GEMM tiling parameters -----------------------------------
#define TM  64
#define TN  64
#define TK  64
#define SLD 68   // padded smem stride (floats), multiple of 4 for float4 reads

// ---------------- Kernel B: x1 @ w1 + b1, exact GELU, accumulate ssq -------
__global__ __launch_bounds__(256) void gemm1_k(
    const float* __restrict__ B, const float* __restrict__ bias, int nrows)
{
    const int KDIM = DIMC, NCOLS = HID;
    __shared__ float As[TK * SLD];
    __shared__ float Bs[TK * SLD];
    __shared__ float csum[TN];

    int t  = threadIdx.x;
    int tx = t & 15, ty = t >> 4;
    int m0 = blockIdx.x * TM;
    int n0 = blockIdx.y * TN;

    float acc[4][4] = {};

    for (int k0 = 0; k0 < KDIM; k0 += TK) {
        // A tile (64x64) -> smem transposed As[k][m]
        #pragma unroll
        for (int i = 0; i < 4; i++) {
            int idx4 = t + i * 256;      // 0..1023 float4s
            int m = idx4 >> 4, k4 = idx4 & 15;
            float4 v = make_float4(0.f, 0.f, 0.f, 0.f);
            if (m0 + m < nrows)
                v = *(const float4*)(g_x1 + (size_t)(m0 + m) * KDIM + k0 + k4 * 4);
            As[(4*k4 + 0) * SLD + m] = v.x;
            As[(4*k4 + 1) * SLD + m] = v.y;
            As[(4*k4 + 2) * SLD + m] = v.z;
            As[(4*k4 + 3) * SLD + m] = v.w;
        }
        // B tile (64x64) -> Bs[k][n]
        #pragma unroll
        for (int i = 0; i < 4; i++) {
            int idx4 = t + i * 256;
            int k = idx4 >> 4, n4 = idx4 & 15;
            float4 v = *(const float4*)(B + (size_t)(k0 + k) * NCOLS + n0 + n4 * 4);
            *(float4*)(Bs + k * SLD + n4 * 4) = v;
        }
        __syncthreads();
        #pragma unroll 8
        for (int k = 0; k < TK; k++) {
            float4 a4 = *(const float4*)(As + k * SLD + ty * 4);
            float4 b4 = *(const float4*)(Bs + k * SLD + tx * 4);
            float av[4] = {a4.x, a4.y, a4.z, a4.w};
            float bv[4] = {b4.x, b4.y, b4.z, b4.w};
            #pragma unroll
            for (int i = 0; i < 4; i++)
                #pragma unroll
                for (int j = 0; j < 4; j++)
                    acc[i][j] = fmaf(av[i], bv[j], acc[i][j]);
        }
        __syncthreads();
    }

    if (t < TN) csum[t] = 0.f;
    __syncthreads();

    float colsq[4] = {0.f, 0.f, 0.f, 0.f};
    #pragma unroll
    for (int i = 0; i < 4; i++) {
        int m = m0 + ty * 4 + i;
        bool ok = (m < nrows);
        #pragma unroll
        for (int j = 0; j < 4; j++) {
            int n = n0 + tx * 4 + j;
            float v = acc[i][j] + bias[n];
            float gl = 0.5f * v * (1.f + erff(v * 0.70710678118654752f));
            if (ok) {
                g_h[(size_t)m * NCOLS + n] = gl;
                colsq[j] += gl * gl;
            }
        }
    }
    #pragma unroll
    for (int j = 0; j < 4; j++) atomicAdd(&csum[tx * 4 + j], colsq[j]);
    __syncthreads();
    if (t < TN) atomicAdd(&g_ssq[n0 + t], csum[t]);
}

// ---------------- Kernel C1: GRN channel scale s = grn_g * nx + 1 ----------
__global__ void grn_scale_k(const float* __restrict__ grn_g)
{
    int c = threadIdx.x;            // 512 threads, 1 block
    float gx = sqrtf(g_ssq[c]);
    __shared__ float red[16];
    __shared__ float mean_s;
    float v = gx;
    #pragma unroll
    for (int o = 16; o; o >>= 1) v += __shfl_xor_sync(0xffffffffu, v, o);
    if ((c & 31) == 0) red[c >> 5] = v;
    __syncthreads();
    if (c < 16) {
        float w = red[c];
        #pragma unroll
        for (int o = 8; o; o >>= 1) w += __shfl_xor_sync(0xffffu, w, o);
        if (c == 0) mean_s = w * (1.f / HID);
    }
    __syncthreads();
    float nx = gx / (mean_s + 1e-6f);
    g_s[c] = grn_g[c] * nx + 1.0f;
}

// ---------------- Kernel C2: w2' = diag(s) @ w2 ----------------------------
__global__ void build_w2p_k(const float* __restrict__ w2)
{
    int idx = blockIdx.x * blockDim.x + threadIdx.x;   // 65536 elems
    if (idx < HID * DIMC) g_w2p[idx] = g_s[idx >> 7] * w2[idx];
}

// ---------------- Kernel C3: b2' = grn_b @ w2 + b2 -------------------------
__global__ void build_b2p_k(const float* __restrict__ grn_b,
                            const float* __restrict__ w2,
                            const float* __restrict__ b2)
{
    int c = threadIdx.x;            // 128 threads, 1 block
    float acc = 0.f;
    for (int k = 0; k < HID; k++) acc = fmaf(grn_b[k], w2[k * DIMC + c], acc);
    g_b2p[c] = b2[c] + acc;
}

// ---------------- Kernel D: h @ w2' + b2' + feats --------------------------
__global__ __launch_bounds__(256) void gemm2_k(
    const float* __restrict__ feats, float* __restrict__ out, int nrows)
{
    const int KDIM = HID, NCOLS = DIMC;
    __shared__ float As[TK * SLD];
    __shared__ float Bs[TK * SLD];

    int t  = threadIdx.x;
    int tx = t & 15, ty = t >> 4;
    int m0 = blockIdx.x * TM;
    int n0 = blockIdx.y * TN;

    float acc[4][4] = {};

    for (int k0 = 0; k0 < KDIM; k0 += TK) {
        #pragma unroll
        for (int i = 0; i < 4; i++) {
            int idx4 = t + i * 256;
            int m = idx4 >> 4, k4 = idx4 & 15;
            float4 v = make_float4(0.f, 0.f, 0.f, 0.f);
            if (m0 + m < nrows)
                v = *(const float4*)(g_h + (size_t)(m0 + m) * KDIM + k0 + k4 * 4);
            As[(4*k4 + 0) * SLD + m] = v.x;
            As[(4*k4 + 1) * SLD + m] = v.y;
            As[(4*k4 + 2) * SLD + m] = v.z;
            As[(4*k4 + 3) * SLD + m] = v.w;
        }
        #pragma unroll
        for (int i = 0; i < 4; i++) {
            int idx4 = t + i * 256;
            int k = idx4 >> 4, n4 = idx4 & 15;
            float4 v = *(const float4*)(g_w2p + (size_t)(k0 + k) * NCOLS + n0 + n4 * 4);
            *(float4*)(Bs + k * SLD + n4 * 4) = v;
        }
        __syncthreads();
        #pragma unroll 8
        for (int k = 0; k < TK; k++) {
            float4 a4 = *(const float4*)(As + k * SLD + ty * 4);
            float4 b4 = *(const float4*)(Bs + k * SLD + tx * 4);
            float av[4] = {a4.x, a4.y, a4.z, a4.w};
            float bv[4] = {b4.x, b4.y, b4.z, b4.w};
            #pragma unroll
            for (int i = 0; i < 4; i++)
                #pragma unroll
                for (int j = 0; j < 4; j++)
                    acc[i][j] = fmaf(av[i], bv[j], acc[i][j]);
        }
        __syncthreads();
    }

    #pragma unroll
    for (int i = 0; i < 4; i++) {
        int m = m0 + ty * 4 + i;
        if (m >= nrows) continue;
        #pragma unroll
        for (int j = 0; j < 4; j++) {
            int n = n0 + tx * 4 + j;
            out[(size_t)m * NCOLS + n] =
                acc[i][j] + g_b2p[n] + feats[(size_t)m * NCOLS + n];
        }
    }
}

// ---------------------------------------------------------------------------
extern "C" void kernel_launch(void* const* d_in, const int* in_sizes, int n_in,
                              void* d_out, int out_size)
{
    const float* feats = (const float*)d_in[0];
    const int*   nbr   = (const int*)  d_in[1];
    const float* dw_w  = (const float*)d_in[2];
    const float* dw_b  = (const float*)d_in[3];
    const float* ln_g  = (const float*)d_in[4];
    const float* ln_b  = (const float*)d_in[5];
    const float* w1    = (const float*)d_in[6];
    const float* b1    = (const float*)d_in[7];
    const float* grn_g = (const float*)d_in[8];
    const float* grn_b = (const float*)d_in[9];
    const float* w2    = (const float*)d_in[10];
    const float* b2    = (const float*)d_in[11];
    float* out = (float*)d_out;

    int n = in_sizes[0] / DIMC;

    zero_ssq_k<<<1, HID>>>();

    int warps_total = n;                       // one warp per site
    int blocks_a = (warps_total * 32 + 255) / 256;
    dwconv_ln_k<<<blocks_a, 256>>>(feats, nbr, dw_w, dw_b, ln_g, ln_b, n);

    dim3 g1((n + TM - 1) / TM, HID / TN);
    gemm1_k<<<g1, 256>>>(w1, b1, n);

    grn_scale_k<<<1, HID>>>(grn_g);
    build_w2p_k<<<(HID * DIMC + 255) / 256, 256>>>(w2);
    build_b2p_k<<<1, DIMC>>>(grn_b, w2, b2);

    dim3 g2((n + TM - 1) / TM, DIMC / TN);
    gemm2_k<<<g2, 256>>>(feats, out, n);
}

// round 5
// speedup vs baseline: 1.4612x; 1.4612x over previous
#include <cuda_runtime.h>
#include <cuda_bf16.h>
#include <math.h>
#include <stdint.h>

// Problem constants (fixed by the dataset)
#define NMAX   100000
#define DIMC   128
#define HID    512
#define KTAPS  343

// ---------------- scratch (device globals; no allocation allowed) ----------
__device__ __nv_bfloat16 g_x1_hi[(size_t)NMAX * DIMC];   // post dwconv+LN, hi
__device__ __nv_bfloat16 g_x1_lo[(size_t)NMAX * DIMC];   // post dwconv+LN, lo
__device__ __nv_bfloat16 g_w1t_hi[HID * DIMC];           // w1 transposed [n][k], hi
__device__ __nv_bfloat16 g_w1t_lo[HID * DIMC];           // w1 transposed [n][k], lo
__device__ __nv_bfloat16 g_h_hi[(size_t)NMAX * HID];     // gelu(h), hi (102.4 MB)
__device__ __nv_bfloat16 g_h_lo[(size_t)NMAX * HID];     // gelu(h), lo (102.4 MB)
__device__ float g_ssq[HID];
__device__ float g_s  [HID];                             // GRN scale: grn_g*nx + 1
__device__ __nv_bfloat16 g_w2t_hi[DIMC * HID];           // w2' transposed [n][k], hi
__device__ __nv_bfloat16 g_w2t_lo[DIMC * HID];           // w2' transposed [n][k], lo
__device__ float g_b2p[DIMC];                            // grn_b @ w2 + b2

// ======================= helpers ===========================================
__device__ __forceinline__ uint32_t smem_u32(const void* p) {
    uint32_t a;
    asm("{ .reg .u64 t; cvta.to.shared.u64 t, %1; cvt.u32.u64 %0, t; }" : "=r"(a) : "l"(p));
    return a;
}
__device__ __forceinline__ void split_bf16(float v, __nv_bfloat16& hi, __nv_bfloat16& lo) {
    hi = __float2bfloat16_rn(v);
    lo = __float2bfloat16_rn(v - __bfloat162float(hi));
}
__device__ __forceinline__ float gelu_exact(float v) {
    return 0.5f * v * (1.0f + erff(v * 0.70710678118654752f));
}
// swizzled byte offset within a [rows][64 bf16] (128B/row) smem tile
__device__ __forceinline__ uint32_t sw_off(int row, int u) {   // u = 16B unit 0..7
    return (uint32_t)((row * 128 + u * 16) ^ ((row & 7) << 4));
}
__device__ __forceinline__ void ldsm4(uint32_t* r, uint32_t addr) {
    asm volatile("ldmatrix.sync.aligned.m8n8.x4.shared.b16 {%0,%1,%2,%3}, [%4];"
        : "=r"(r[0]), "=r"(r[1]), "=r"(r[2]), "=r"(r[3]) : "r"(addr));
}
__device__ __forceinline__ void mma16816(float* c, const uint32_t* a, const uint32_t* b) {
    asm volatile("mma.sync.aligned.m16n8k16.row.col.f32.bf16.bf16.f32 "
        "{%0,%1,%2,%3}, {%4,%5,%6,%7}, {%8,%9}, {%0,%1,%2,%3};"
        : "+f"(c[0]), "+f"(c[1]), "+f"(c[2]), "+f"(c[3])
        : "r"(a[0]), "r"(a[1]), "r"(a[2]), "r"(a[3]), "r"(b[0]), "r"(b[1]));
}

// ---------------------------------------------------------------------------
__global__ void zero_ssq_k() { g_ssq[threadIdx.x] = 0.f; }

// ---------------- Kernel A: sparse depthwise conv + LayerNorm -> split bf16
__global__ __launch_bounds__(256) void dwconv_ln_k(
    const float* __restrict__ feats, const int* __restrict__ nbr,
    const float* __restrict__ dw_w, const float* __restrict__ dw_b,
    const float* __restrict__ ln_g, const float* __restrict__ ln_b, int n)
{
    int site = (blockIdx.x * blockDim.x + threadIdx.x) >> 5;
    int lane = threadIdx.x & 31;
    if (site >= n) return;

    const int* row = nbr + (size_t)site * KTAPS;
    float4 acc = make_float4(0.f, 0.f, 0.f, 0.f);

    for (int k0 = 0; k0 < KTAPS; k0 += 32) {
        int k   = k0 + lane;
        int idx = (k < KTAPS) ? row[k] : n;
        unsigned valid = __ballot_sync(0xffffffffu, idx < n);
        while (valid) {
            int b = __ffs(valid) - 1;
            valid &= valid - 1;
            int j  = __shfl_sync(0xffffffffu, idx, b);
            int kk = k0 + b;
            float4 f = *(const float4*)(feats + (size_t)j * DIMC + lane * 4);
            float4 w = *(const float4*)(dw_w + kk * DIMC + lane * 4);
            acc.x = fmaf(f.x, w.x, acc.x);
            acc.y = fmaf(f.y, w.y, acc.y);
            acc.z = fmaf(f.z, w.z, acc.z);
            acc.w = fmaf(f.w, w.w, acc.w);
        }
    }
    float4 bb = *(const float4*)(dw_b + lane * 4);
    acc.x += bb.x; acc.y += bb.y; acc.z += bb.z; acc.w += bb.w;

    float s1 = acc.x + acc.y + acc.z + acc.w;
    float s2 = acc.x*acc.x + acc.y*acc.y + acc.z*acc.z + acc.w*acc.w;
    #pragma unroll
    for (int o = 16; o; o >>= 1) {
        s1 += __shfl_xor_sync(0xffffffffu, s1, o);
        s2 += __shfl_xor_sync(0xffffffffu, s2, o);
    }
    float mean = s1 * (1.f / DIMC);
    float var  = s2 * (1.f / DIMC) - mean * mean;
    float rstd = rsqrtf(var + 1e-6f);

    float4 g = *(const float4*)(ln_g + lane * 4);
    float4 b = *(const float4*)(ln_b + lane * 4);
    float v0 = (acc.x - mean) * rstd * g.x + b.x;
    float v1 = (acc.y - mean) * rstd * g.y + b.y;
    float v2 = (acc.z - mean) * rstd * g.z + b.z;
    float v3 = (acc.w - mean) * rstd * g.w + b.w;

    __nv_bfloat16 h0,l0,h1,l1,h2,l2,h3,l3;
    split_bf16(v0, h0, l0); split_bf16(v1, h1, l1);
    split_bf16(v2, h2, l2); split_bf16(v3, h3, l3);
    size_t o = (size_t)site * DIMC + lane * 4;
    *(__nv_bfloat162*)(g_x1_hi + o)     = __halves2bfloat162(h0, h1);
    *(__nv_bfloat162*)(g_x1_hi + o + 2) = __halves2bfloat162(h2, h3);
    *(__nv_bfloat162*)(g_x1_lo + o)     = __halves2bfloat162(l0, l1);
    *(__nv_bfloat162*)(g_x1_lo + o + 2) = __halves2bfloat162(l2, l3);
}

// ---------------- prep: w1t[n][k] = split(w1[k][n]) ------------------------
__global__ void w1t_prep_k(const float* __restrict__ w1)
{
    int idx = blockIdx.x * blockDim.x + threadIdx.x;   // 65536 = 512*128
    if (idx < HID * DIMC) {
        int nrow = idx >> 7, k = idx & 127;
        __nv_bfloat16 hi, lo;
        split_bf16(w1[(size_t)k * HID + nrow], hi, lo);
        g_w1t_hi[idx] = hi;
        g_w1t_lo[idx] = lo;
    }
}

// ============== shared mainloop pieces (macro-free, inlined) ===============
// Block tile 128(M) x 128(N), 512 threads = 16 warps (4m x 4n), warp 32x32.
// K processed in chunks of 64. smem: Ah,Al,Bh,Bl each [128][64] bf16 = 16KB.

struct Frag { float acc[2][4][4]; };   // [mf][nf][reg]

__device__ __forceinline__ void chunk_load(
    char* sAh, char* sAl, char* sBh, char* sBl,
    const __nv_bfloat16* Ahi, const __nv_bfloat16* Alo, size_t a_stride,  // elements
    const __nv_bfloat16* Bhi, const __nv_bfloat16* Blo, size_t b_stride,
    int m0, int n_valid, int nb0, int kc, int tid)
{
    #pragma unroll
    for (int i = 0; i < 2; i++) {
        int idx = tid + i * 512;          // 0..1023
        int row = idx >> 3, u = idx & 7;
        uint32_t so = sw_off(row, u);
        // A
        uint4 vh = make_uint4(0,0,0,0), vl = make_uint4(0,0,0,0);
        if (m0 + row < n_valid) {
            const char* pa = (const char*)(Ahi + (size_t)(m0 + row) * a_stride) + kc * 128;
            const char* pb = (const char*)(Alo + (size_t)(m0 + row) * a_stride) + kc * 128;
            vh = *(const uint4*)(pa + u * 16);
            vl = *(const uint4*)(pb + u * 16);
        }
        *(uint4*)(sAh + so) = vh;
        *(uint4*)(sAl + so) = vl;
        // B (always full)
        {
            const char* pa = (const char*)(Bhi + (size_t)(nb0 + row) * b_stride) + kc * 128;
            const char* pb = (const char*)(Blo + (size_t)(nb0 + row) * b_stride) + kc * 128;
            *(uint4*)(sBh + so) = *(const uint4*)(pa + u * 16);
            *(uint4*)(sBl + so) = *(const uint4*)(pb + u * 16);
        }
    }
}

__device__ __forceinline__ void chunk_mma(
    Frag& F, uint32_t uAh, uint32_t uAl, uint32_t uBh, uint32_t uBl,
    int wm, int wn, int lane)
{
    int lr = lane & 15, lh = lane >> 4;
    #pragma unroll
    for (int ks = 0; ks < 4; ks++) {
        int u = ks * 2 + lh;
        uint32_t ah[2][4], al[2][4];
        #pragma unroll
        for (int mf = 0; mf < 2; mf++) {
            int row = wm * 32 + mf * 16 + lr;
            ldsm4(ah[mf], uAh + sw_off(row, u));
            ldsm4(al[mf], uAl + sw_off(row, u));
        }
        uint32_t bh[4][2], bl[4][2], t[4];
        #pragma unroll
        for (int nh = 0; nh < 2; nh++) {
            int row = wn * 32 + nh * 16 + lr;
            ldsm4(t, uBh + sw_off(row, u));
            bh[nh*2+0][0] = t[0]; bh[nh*2+0][1] = t[2];
            bh[nh*2+1][0] = t[1]; bh[nh*2+1][1] = t[3];
            ldsm4(t, uBl + sw_off(row, u));
            bl[nh*2+0][0] = t[0]; bl[nh*2+0][1] = t[2];
            bl[nh*2+1][0] = t[1]; bl[nh*2+1][1] = t[3];
        }
        #pragma unroll
        for (int mf = 0; mf < 2; mf++)
            #pragma unroll
            for (int nf = 0; nf < 4; nf++) {
                mma16816(F.acc[mf][nf], ah[mf], bh[nf]);
                mma16816(F.acc[mf][nf], ah[mf], bl[nf]);
                mma16816(F.acc[mf][nf], al[mf], bh[nf]);
            }
    }
}

// ---------------- Kernel B: GEMM1  h = gelu(x1 @ w1 + b1), + ssq -----------
__global__ __launch_bounds__(512) void gemm1_tc(const float* __restrict__ b1, int n)
{
    extern __shared__ char smem[];
    char* sAh = smem;
    char* sAl = smem + 16384;
    char* sBh = smem + 32768;
    char* sBl = smem + 49152;
    __shared__ float scs[128];

    int tid = threadIdx.x;
    int wid = tid >> 5, lane = tid & 31;
    int wm = wid >> 2, wn = wid & 3;
    int m0 = blockIdx.x * 128;
    int n0 = blockIdx.y * 128;

    if (tid < 128) scs[tid] = 0.f;

    uint32_t uAh = smem_u32(sAh), uAl = smem_u32(sAl);
    uint32_t uBh = smem_u32(sBh), uBl = smem_u32(sBl);

    Frag F;
    #pragma unroll
    for (int mf = 0; mf < 2; mf++)
        #pragma unroll
        for (int nf = 0; nf < 4; nf++)
            #pragma unroll
            for (int r = 0; r < 4; r++) F.acc[mf][nf][r] = 0.f;

    for (int kc = 0; kc < DIMC / 64; kc++) {
        __syncthreads();
        chunk_load(sAh, sAl, sBh, sBl,
                   g_x1_hi, g_x1_lo, DIMC,
                   g_w1t_hi, g_w1t_lo, DIMC,
                   m0, n, n0, kc, tid);
        __syncthreads();
        chunk_mma(F, uAh, uAl, uBh, uBl, wm, wn, lane);
    }

    // epilogue: bias + GELU, split-bf16 store, per-column ssq
    int g = lane >> 2, q = lane & 3;
    float csq[8] = {0,0,0,0,0,0,0,0};
    #pragma unroll
    for (int mf = 0; mf < 2; mf++) {
        #pragma unroll
        for (int nf = 0; nf < 4; nf++) {
            int col = n0 + wn * 32 + nf * 8 + q * 2;
            float bia0 = b1[col], bia1 = b1[col + 1];
            #pragma unroll
            for (int half = 0; half < 2; half++) {
                int m = m0 + wm * 32 + mf * 16 + g + half * 8;
                if (m < n) {
                    float v0 = gelu_exact(F.acc[mf][nf][half*2+0] + bia0);
                    float v1 = gelu_exact(F.acc[mf][nf][half*2+1] + bia1);
                    __nv_bfloat16 h0,l0,h1,l1;
                    split_bf16(v0, h0, l0); split_bf16(v1, h1, l1);
                    size_t o = (size_t)m * HID + col;
                    *(__nv_bfloat162*)(g_h_hi + o) = __halves2bfloat162(h0, h1);
                    *(__nv_bfloat162*)(g_h_lo + o) = __halves2bfloat162(l0, l1);
                    csq[nf*2+0] += v0 * v0;
                    csq[nf*2+1] += v1 * v1;
                }
            }
        }
    }
    __syncthreads();   // scs zero-init visible
    #pragma unroll
    for (int nf = 0; nf < 4; nf++) {
        atomicAdd(&scs[wn * 32 + nf * 8 + q * 2],     csq[nf*2+0]);
        atomicAdd(&scs[wn * 32 + nf * 8 + q * 2 + 1], csq[nf*2+1]);
    }
    __syncthreads();
    if (tid < 128) atomicAdd(&g_ssq[n0 + tid], scs[tid]);
}

// ---------------- Kernel D1: GRN channel scale -----------------------------
__global__ void grn_scale_k(const float* __restrict__ grn_g)
{
    int c = threadIdx.x;            // 512 threads, 1 block
    float gx = sqrtf(g_ssq[c]);
    __shared__ float red[16];
    __shared__ float mean_s;
    float v = gx;
    #pragma unroll
    for (int o = 16; o; o >>= 1) v += __shfl_xor_sync(0xffffffffu, v, o);
    if ((c & 31) == 0) red[c >> 5] = v;
    __syncthreads();
    if (c < 16) {
        float w = red[c];
        #pragma unroll
        for (int o = 8; o; o >>= 1) w += __shfl_xor_sync(0xffffu, w, o);
        if (c == 0) mean_s = w * (1.f / HID);
    }
    __syncthreads();
    float nx = gx / (mean_s + 1e-6f);
    g_s[c] = grn_g[c] * nx + 1.0f;
}

// ---------------- Kernel D2: w2t[n][k] = split(s[k]*w2[k][n]) --------------
__global__ void build_w2t_k(const float* __restrict__ w2)
{
    int idx = blockIdx.x * blockDim.x + threadIdx.x;   // 65536 = 128*512
    if (idx < DIMC * HID) {
        int nrow = idx >> 9, k = idx & 511;
        __nv_bfloat16 hi, lo;
        split_bf16(g_s[k] * w2[(size_t)k * DIMC + nrow], hi, lo);
        g_w2t_hi[idx] = hi;
        g_w2t_lo[idx] = lo;
    }
}

// ---------------- Kernel D3: b2' = grn_b @ w2 + b2 -------------------------
__global__ void build_b2p_k(const float* __restrict__ grn_b,
                            const float* __restrict__ w2,
                            const float* __restrict__ b2)
{
    int c = threadIdx.x;            // 128 threads
    float acc = 0.f;
    for (int k = 0; k < HID; k++) acc = fmaf(grn_b[k], w2[(size_t)k * DIMC + c], acc);
    g_b2p[c] = b2[c] + acc;
}

// ---------------- Kernel E: GEMM2  out = h @ w2' + b2' + feats -------------
__global__ __launch_bounds__(512) void gemm2_tc(
    const float* __restrict__ feats, float* __restrict__ out, int n)
{
    extern __shared__ char smem[];
    char* sAh = smem;
    char* sAl = smem + 16384;
    char* sBh = smem + 32768;
    char* sBl = smem + 49152;

    int tid = threadIdx.x;
    int wid = tid >> 5, lane = tid & 31;
    int wm = wid >> 2, wn = wid & 3;
    int m0 = blockIdx.x * 128;

    uint32_t uAh = smem_u32(sAh), uAl = smem_u32(sAl);
    uint32_t uBh = smem_u32(sBh), uBl = smem_u32(sBl);

    Frag F;
    #pragma unroll
    for (int mf = 0; mf < 2; mf++)
        #pragma unroll
        for (int nf = 0; nf < 4; nf++)
            #pragma unroll
            for (int r = 0; r < 4; r++) F.acc[mf][nf][r] = 0.f;

    for (int kc = 0; kc < HID / 64; kc++) {
        __syncthreads();
        chunk_load(sAh, sAl, sBh, sBl,
                   g_h_hi, g_h_lo, HID,
                   g_w2t_hi, g_w2t_lo, HID,
                   m0, n, 0, kc, tid);
        __syncthreads();
        chunk_mma(F, uAh, uAl, uBh, uBl, wm, wn, lane);
    }

    // epilogue: + b2' + feats residual, fp32 out
    int g = lane >> 2, q = lane & 3;
    #pragma unroll
    for (int mf = 0; mf < 2; mf++) {
        #pragma unroll
        for (int nf = 0; nf < 4; nf++) {
            int col = wn * 32 + nf * 8 + q * 2;
            float b0 = g_b2p[col], b1v = g_b2p[col + 1];
            #pragma unroll
            for (int half = 0; half < 2; half++) {
                int m = m0 + wm * 32 + mf * 16 + g + half * 8;
                if (m < n) {
                    size_t o = (size_t)m * DIMC + col;
                    float2 fr = *(const float2*)(feats + o);
                    float2 ov;
                    ov.x = F.acc[mf][nf][half*2+0] + b0  + fr.x;
                    ov.y = F.acc[mf][nf][half*2+1] + b1v + fr.y;
                    *(float2*)(out + o) = ov;
                }
            }
        }
    }
}

// ---------------------------------------------------------------------------
extern "C" void kernel_launch(void* const* d_in, const int* in_sizes, int n_in,
                              void* d_out, int out_size)
{
    const float* feats = (const float*)d_in[0];
    const int*   nbr   = (const int*)  d_in[1];
    const float* dw_w  = (const float*)d_in[2];
    const float* dw_b  = (const float*)d_in[3];
    const float* ln_g  = (const float*)d_in[4];
    const float* ln_b  = (const float*)d_in[5];
    const float* w1    = (const float*)d_in[6];
    const float* b1    = (const float*)d_in[7];
    const float* grn_g = (const float*)d_in[8];
    const float* grn_b = (const float*)d_in[9];
    const float* w2    = (const float*)d_in[10];
    const float* b2    = (const float*)d_in[11];
    float* out = (float*)d_out;

    int n = in_sizes[0] / DIMC;

    const int SMEM = 64 * 1024;
    cudaFuncSetAttribute(gemm1_tc, cudaFuncAttributeMaxDynamicSharedMemorySize, SMEM);
    cudaFuncSetAttribute(gemm2_tc, cudaFuncAttributeMaxDynamicSharedMemorySize, SMEM);

    zero_ssq_k<<<1, HID>>>();

    int blocks_a = (n * 32 + 255) / 256;
    dwconv_ln_k<<<blocks_a, 256>>>(feats, nbr, dw_w, dw_b, ln_g, ln_b, n);

    w1t_prep_k<<<(HID * DIMC + 255) / 256, 256>>>(w1);

    int mtiles = (n + 127) / 128;
    dim3 g1(mtiles, HID / 128);
    gemm1_tc<<<g1, 512, SMEM>>>(b1, n);

    grn_scale_k<<<1, HID>>>(grn_g);
    build_w2t_k<<<(DIMC * HID + 255) / 256, 256>>>(w2);
    build_b2p_k<<<1, DIMC>>>(grn_b, w2, b2);

    gemm2_tc<<<mtiles, 512, SMEM>>>(feats, out, n);
}

// round 6
// speedup vs baseline: 1.6748x; 1.1462x over previous
#include <cuda_runtime.h>
#include <cuda_bf16.h>
#include <math.h>
#include <stdint.h>

// Problem constants (fixed by the dataset)
#define NMAX   100000
#define DIMC   128
#define HID    512
#define KTAPS  343

// ---------------- scratch (device globals; no allocation allowed) ----------
__device__ __nv_bfloat16 g_x1_hi[(size_t)NMAX * DIMC];
__device__ __nv_bfloat16 g_x1_lo[(size_t)NMAX * DIMC];
__device__ __nv_bfloat16 g_w1t_hi[HID * DIMC];          // w1^T [n][k]
__device__ __nv_bfloat16 g_w1t_lo[HID * DIMC];
__device__ __nv_bfloat16 g_h_hi[(size_t)NMAX * HID];
__device__ __nv_bfloat16 g_h_lo[(size_t)NMAX * HID];
__device__ float g_ssq[HID];
__device__ float g_s  [HID];
__device__ __nv_bfloat16 g_w2t_hi[DIMC * HID];          // (diag(s)w2)^T [n][k]
__device__ __nv_bfloat16 g_w2t_lo[DIMC * HID];
__device__ float g_b2p[DIMC];

// ======================= helpers ===========================================
__device__ __forceinline__ uint32_t smem_u32(const void* p) {
    uint32_t a;
    asm("{ .reg .u64 t; cvta.to.shared.u64 t, %1; cvt.u32.u64 %0, t; }" : "=r"(a) : "l"(p));
    return a;
}
__device__ __forceinline__ void split_bf16(float v, __nv_bfloat16& hi, __nv_bfloat16& lo) {
    hi = __float2bfloat16_rn(v);
    lo = __float2bfloat16_rn(v - __bfloat162float(hi));
}
__device__ __forceinline__ float gelu_exact(float v) {
    return 0.5f * v * (1.0f + erff(v * 0.70710678118654752f));
}
// swizzled byte offset within a [rows][64 bf16] (128B/row) smem tile
__device__ __forceinline__ uint32_t sw_off(int row, int u) {   // u = 16B unit 0..7
    return (uint32_t)((row * 128 + u * 16) ^ ((row & 7) << 4));
}
__device__ __forceinline__ void ldsm4(uint32_t* r, uint32_t addr) {
    asm volatile("ldmatrix.sync.aligned.m8n8.x4.shared.b16 {%0,%1,%2,%3}, [%4];"
        : "=r"(r[0]), "=r"(r[1]), "=r"(r[2]), "=r"(r[3]) : "r"(addr));
}
__device__ __forceinline__ void mma16816(float* c, const uint32_t* a, const uint32_t* b) {
    asm volatile("mma.sync.aligned.m16n8k16.row.col.f32.bf16.bf16.f32 "
        "{%0,%1,%2,%3}, {%4,%5,%6,%7}, {%8,%9}, {%0,%1,%2,%3};"
        : "+f"(c[0]), "+f"(c[1]), "+f"(c[2]), "+f"(c[3])
        : "r"(a[0]), "r"(a[1]), "r"(a[2]), "r"(a[3]), "r"(b[0]), "r"(b[1]));
}
__device__ __forceinline__ void cp16(uint32_t dst, const void* src, bool pred) {
    int sz = pred ? 16 : 0;
    asm volatile("cp.async.cg.shared.global [%0], [%1], 16, %2;"
        :: "r"(dst), "l"(src), "r"(sz));
}
#define CP_COMMIT() asm volatile("cp.async.commit_group;" ::: "memory")
#define CP_WAIT(N)  asm volatile("cp.async.wait_group %0;" :: "n"(N) : "memory")

// ---------------------------------------------------------------------------
__global__ void zero_ssq_k() { g_ssq[threadIdx.x] = 0.f; }

// ---------------- Kernel A: sparse depthwise conv + LayerNorm -> split bf16
__global__ __launch_bounds__(256) void dwconv_ln_k(
    const float* __restrict__ feats, const int* __restrict__ nbr,
    const float* __restrict__ dw_w, const float* __restrict__ dw_b,
    const float* __restrict__ ln_g, const float* __restrict__ ln_b, int n)
{
    int site = (blockIdx.x * blockDim.x + threadIdx.x) >> 5;
    int lane = threadIdx.x & 31;
    if (site >= n) return;

    const int* row = nbr + (size_t)site * KTAPS;
    float4 acc = make_float4(0.f, 0.f, 0.f, 0.f);

    for (int k0 = 0; k0 < KTAPS; k0 += 32) {
        int k   = k0 + lane;
        int idx = (k < KTAPS) ? row[k] : n;
        unsigned valid = __ballot_sync(0xffffffffu, idx < n);
        while (valid) {
            int b = __ffs(valid) - 1;
            valid &= valid - 1;
            int j  = __shfl_sync(0xffffffffu, idx, b);
            int kk = k0 + b;
            float4 f = *(const float4*)(feats + (size_t)j * DIMC + lane * 4);
            float4 w = *(const float4*)(dw_w + kk * DIMC + lane * 4);
            acc.x = fmaf(f.x, w.x, acc.x);
            acc.y = fmaf(f.y, w.y, acc.y);
            acc.z = fmaf(f.z, w.z, acc.z);
            acc.w = fmaf(f.w, w.w, acc.w);
        }
    }
    float4 bb = *(const float4*)(dw_b + lane * 4);
    acc.x += bb.x; acc.y += bb.y; acc.z += bb.z; acc.w += bb.w;

    float s1 = acc.x + acc.y + acc.z + acc.w;
    float s2 = acc.x*acc.x + acc.y*acc.y + acc.z*acc.z + acc.w*acc.w;
    #pragma unroll
    for (int o = 16; o; o >>= 1) {
        s1 += __shfl_xor_sync(0xffffffffu, s1, o);
        s2 += __shfl_xor_sync(0xffffffffu, s2, o);
    }
    float mean = s1 * (1.f / DIMC);
    float var  = s2 * (1.f / DIMC) - mean * mean;
    float rstd = rsqrtf(var + 1e-6f);

    float4 g = *(const float4*)(ln_g + lane * 4);
    float4 b = *(const float4*)(ln_b + lane * 4);
    float v0 = (acc.x - mean) * rstd * g.x + b.x;
    float v1 = (acc.y - mean) * rstd * g.y + b.y;
    float v2 = (acc.z - mean) * rstd * g.z + b.z;
    float v3 = (acc.w - mean) * rstd * g.w + b.w;

    __nv_bfloat16 h0,l0,h1,l1,h2,l2,h3,l3;
    split_bf16(v0, h0, l0); split_bf16(v1, h1, l1);
    split_bf16(v2, h2, l2); split_bf16(v3, h3, l3);
    size_t o = (size_t)site * DIMC + lane * 4;
    *(__nv_bfloat162*)(g_x1_hi + o)     = __halves2bfloat162(h0, h1);
    *(__nv_bfloat162*)(g_x1_hi + o + 2) = __halves2bfloat162(h2, h3);
    *(__nv_bfloat162*)(g_x1_lo + o)     = __halves2bfloat162(l0, l1);
    *(__nv_bfloat162*)(g_x1_lo + o + 2) = __halves2bfloat162(l2, l3);
}

// ---------------- prep: w1t[n][k] = split(w1[k][n]) ------------------------
__global__ void w1t_prep_k(const float* __restrict__ w1)
{
    int idx = blockIdx.x * blockDim.x + threadIdx.x;   // 65536 = 512*128
    if (idx < HID * DIMC) {
        int nrow = idx >> 7, k = idx & 127;
        __nv_bfloat16 hi, lo;
        split_bf16(w1[(size_t)k * HID + nrow], hi, lo);
        g_w1t_hi[idx] = hi;
        g_w1t_lo[idx] = lo;
    }
}

// ============== async chunk loader (generic) ===============================
// Loads one K-chunk (64 cols) of A (128 rows, zero-padded past n_valid) and
// B (brows rows) hi+lo into a swizzled smem stage. One cp.async group.
__device__ __forceinline__ void load_chunk_async(
    uint32_t sAh, uint32_t sAl, uint32_t sBh, uint32_t sBl,
    const __nv_bfloat16* __restrict__ Ahi, const __nv_bfloat16* __restrict__ Alo,
    int a_stride,
    const __nv_bfloat16* __restrict__ Bhi, const __nv_bfloat16* __restrict__ Blo,
    int b_stride, int brows,
    int m0, int n_valid, int nb0, int kc, int tid)
{
    // A: 128 rows x 8 units
    #pragma unroll
    for (int i = 0; i < 2; i++) {
        int idx = tid + i * 512;
        int row = idx >> 3, u = idx & 7;
        bool ok = (m0 + row < n_valid);
        size_t go = (size_t)(m0 + row) * a_stride + kc * 64 + u * 8;
        uint32_t so = sw_off(row, u);
        cp16(sAh + so, Ahi + go, ok);
        cp16(sAl + so, Alo + go, ok);
    }
    // B: brows x 8 units
    for (int idx = tid; idx < brows * 8; idx += 512) {
        int row = idx >> 3, u = idx & 7;
        size_t go = (size_t)(nb0 + row) * b_stride + kc * 64 + u * 8;
        uint32_t so = sw_off(row, u);
        cp16(sBh + so, Bhi + go, true);
        cp16(sBl + so, Blo + go, true);
    }
    CP_COMMIT();
}

// ---------------- Kernel B: GEMM1  h = gelu(x1 @ w1 + b1), + ssq -----------
// Block 128M x 256N, K=128 (2 chunks of 64), 512 thr = 16 warps (4m x 4n),
// warp tile 32x64. smem: 2 stages x (A 32KB + B 64KB) = 192KB.
__global__ __launch_bounds__(512) void gemm1_tc(const float* __restrict__ b1, int n)
{
    extern __shared__ char smem[];
    const int STG = 98304;
    __shared__ float scs[256];

    int tid = threadIdx.x;
    int wid = tid >> 5, lane = tid & 31;
    int wm = wid >> 2, wn = wid & 3;
    int lr = lane & 15, lh = lane >> 4;
    int m0 = blockIdx.x * 128;
    int n0 = blockIdx.y * 256;

    if (tid < 256) scs[tid] = 0.f;

    uint32_t base = smem_u32(smem);
    // stage s: Ah = base+s*STG, Al +16384, Bh +32768, Bl +65536 (32KB)

    float acc[2][8][4];
    #pragma unroll
    for (int mf = 0; mf < 2; mf++)
        #pragma unroll
        for (int nf = 0; nf < 8; nf++)
            #pragma unroll
            for (int r = 0; r < 4; r++) acc[mf][nf][r] = 0.f;

    // issue both chunks' loads up front
    #pragma unroll
    for (int kc = 0; kc < 2; kc++) {
        uint32_t sb = base + kc * STG;
        load_chunk_async(sb, sb + 16384, sb + 32768, sb + 65536,
                         g_x1_hi, g_x1_lo, DIMC,
                         g_w1t_hi, g_w1t_lo, DIMC, 256,
                         m0, n, n0, kc, tid);
    }

    #pragma unroll
    for (int kc = 0; kc < 2; kc++) {
        if (kc == 0) { CP_WAIT(1); } else { CP_WAIT(0); }
        __syncthreads();
        uint32_t sb = base + kc * STG;
        uint32_t uAh = sb, uAl = sb + 16384, uBh = sb + 32768, uBl = sb + 65536;
        #pragma unroll
        for (int ks = 0; ks < 4; ks++) {
            int u = ks * 2 + lh;
            uint32_t ah[2][4], al[2][4];
            #pragma unroll
            for (int mf = 0; mf < 2; mf++) {
                int row = wm * 32 + mf * 16 + lr;
                ldsm4(ah[mf], uAh + sw_off(row, u));
                ldsm4(al[mf], uAl + sw_off(row, u));
            }
            #pragma unroll
            for (int nh = 0; nh < 4; nh++) {
                int row = wn * 64 + nh * 16 + lr;
                uint32_t t[4], bh[2][2], bl[2][2];
                ldsm4(t, uBh + sw_off(row, u));
                bh[0][0] = t[0]; bh[0][1] = t[2];
                bh[1][0] = t[1]; bh[1][1] = t[3];
                ldsm4(t, uBl + sw_off(row, u));
                bl[0][0] = t[0]; bl[0][1] = t[2];
                bl[1][0] = t[1]; bl[1][1] = t[3];
                #pragma unroll
                for (int mf = 0; mf < 2; mf++)
                    #pragma unroll
                    for (int j = 0; j < 2; j++) {
                        int nf = nh * 2 + j;
                        mma16816(acc[mf][nf], ah[mf], bh[j]);
                        mma16816(acc[mf][nf], ah[mf], bl[j]);
                        mma16816(acc[mf][nf], al[mf], bh[j]);
                    }
            }
        }
        __syncthreads();
    }

    // epilogue: bias + GELU, split-bf16 store, per-column ssq
    int g = lane >> 2, q = lane & 3;
    float csq[16];
    #pragma unroll
    for (int i = 0; i < 16; i++) csq[i] = 0.f;
    #pragma unroll
    for (int mf = 0; mf < 2; mf++) {
        #pragma unroll
        for (int nf = 0; nf < 8; nf++) {
            int col = n0 + wn * 64 + nf * 8 + q * 2;
            float bia0 = b1[col], bia1 = b1[col + 1];
            #pragma unroll
            for (int half = 0; half < 2; half++) {
                int m = m0 + wm * 32 + mf * 16 + g + half * 8;
                if (m < n) {
                    float v0 = gelu_exact(acc[mf][nf][half*2+0] + bia0);
                    float v1 = gelu_exact(acc[mf][nf][half*2+1] + bia1);
                    __nv_bfloat16 h0,l0,h1,l1;
                    split_bf16(v0, h0, l0); split_bf16(v1, h1, l1);
                    size_t o = (size_t)m * HID + col;
                    *(__nv_bfloat162*)(g_h_hi + o) = __halves2bfloat162(h0, h1);
                    *(__nv_bfloat162*)(g_h_lo + o) = __halves2bfloat162(l0, l1);
                    csq[nf*2+0] += v0 * v0;
                    csq[nf*2+1] += v1 * v1;
                }
            }
        }
    }
    __syncthreads();
    #pragma unroll
    for (int nf = 0; nf < 8; nf++) {
        atomicAdd(&scs[wn * 64 + nf * 8 + q * 2],     csq[nf*2+0]);
        atomicAdd(&scs[wn * 64 + nf * 8 + q * 2 + 1], csq[nf*2+1]);
    }
    __syncthreads();
    if (tid < 256) atomicAdd(&g_ssq[n0 + tid], scs[tid]);
}

// ---------------- Kernel D1: GRN channel scale -----------------------------
__global__ void grn_scale_k(const float* __restrict__ grn_g)
{
    int c = threadIdx.x;            // 512 threads, 1 block
    float gx = sqrtf(g_ssq[c]);
    __shared__ float red[16];
    __shared__ float mean_s;
    float v = gx;
    #pragma unroll
    for (int o = 16; o; o >>= 1) v += __shfl_xor_sync(0xffffffffu, v, o);
    if ((c & 31) == 0) red[c >> 5] = v;
    __syncthreads();
    if (c < 16) {
        float w = red[c];
        #pragma unroll
        for (int o = 8; o; o >>= 1) w += __shfl_xor_sync(0xffffu, w, o);
        if (c == 0) mean_s = w * (1.f / HID);
    }
    __syncthreads();
    float nx = gx / (mean_s + 1e-6f);
    g_s[c] = grn_g[c] * nx + 1.0f;
}

// ---------------- Kernel D2: w2t[n][k] = split(s[k]*w2[k][n]) --------------
__global__ void build_w2t_k(const float* __restrict__ w2)
{
    int idx = blockIdx.x * blockDim.x + threadIdx.x;   // 65536 = 128*512
    if (idx < DIMC * HID) {
        int nrow = idx >> 9, k = idx & 511;
        __nv_bfloat16 hi, lo;
        split_bf16(g_s[k] * w2[(size_t)k * DIMC + nrow], hi, lo);
        g_w2t_hi[idx] = hi;
        g_w2t_lo[idx] = lo;
    }
}

// ---------------- Kernel D3: b2' = grn_b @ w2 + b2 -------------------------
__global__ void build_b2p_k(const float* __restrict__ grn_b,
                            const float* __restrict__ w2,
                            const float* __restrict__ b2)
{
    int c = threadIdx.x;            // 128 threads
    float acc = 0.f;
    for (int k = 0; k < HID; k++) acc = fmaf(grn_b[k], w2[(size_t)k * DIMC + c], acc);
    g_b2p[c] = b2[c] + acc;
}

// ---------------- Kernel E: GEMM2  out = h @ w2' + b2' + feats -------------
// Block 128M x 128N, K=512 (8 chunks, 2-stage ring), 512 thr, warp 32x32.
__global__ __launch_bounds__(512) void gemm2_tc(
    const float* __restrict__ feats, float* __restrict__ out, int n)
{
    extern __shared__ char smem[];
    const int STG = 65536;

    int tid = threadIdx.x;
    int wid = tid >> 5, lane = tid & 31;
    int wm = wid >> 2, wn = wid & 3;
    int lr = lane & 15, lh = lane >> 4;
    int m0 = blockIdx.x * 128;

    uint32_t base = smem_u32(smem);
    // stage s: Ah = base+s*STG, Al +16384, Bh +32768, Bl +49152 (16KB)

    float acc[2][4][4];
    #pragma unroll
    for (int mf = 0; mf < 2; mf++)
        #pragma unroll
        for (int nf = 0; nf < 4; nf++)
            #pragma unroll
            for (int r = 0; r < 4; r++) acc[mf][nf][r] = 0.f;

    {
        uint32_t sb = base;
        load_chunk_async(sb, sb + 16384, sb + 32768, sb + 49152,
                         g_h_hi, g_h_lo, HID,
                         g_w2t_hi, g_w2t_lo, HID, 128,
                         m0, n, 0, 0, tid);
    }

    for (int kc = 0; kc < 8; kc++) {
        if (kc < 7) {
            uint32_t sb = base + ((kc + 1) & 1) * STG;
            load_chunk_async(sb, sb + 16384, sb + 32768, sb + 49152,
                             g_h_hi, g_h_lo, HID,
                             g_w2t_hi, g_w2t_lo, HID, 128,
                             m0, n, 0, kc + 1, tid);
            CP_WAIT(1);
        } else {
            CP_WAIT(0);
        }
        __syncthreads();

        uint32_t sb = base + (kc & 1) * STG;
        uint32_t uAh = sb, uAl = sb + 16384, uBh = sb + 32768, uBl = sb + 49152;
        #pragma unroll
        for (int ks = 0; ks < 4; ks++) {
            int u = ks * 2 + lh;
            uint32_t ah[2][4], al[2][4];
            #pragma unroll
            for (int mf = 0; mf < 2; mf++) {
                int row = wm * 32 + mf * 16 + lr;
                ldsm4(ah[mf], uAh + sw_off(row, u));
                ldsm4(al[mf], uAl + sw_off(row, u));
            }
            #pragma unroll
            for (int nh = 0; nh < 2; nh++) {
                int row = wn * 32 + nh * 16 + lr;
                uint32_t t[4], bh[2][2], bl[2][2];
                ldsm4(t, uBh + sw_off(row, u));
                bh[0][0] = t[0]; bh[0][1] = t[2];
                bh[1][0] = t[1]; bh[1][1] = t[3];
                ldsm4(t, uBl + sw_off(row, u));
                bl[0][0] = t[0]; bl[0][1] = t[2];
                bl[1][0] = t[1]; bl[1][1] = t[3];
                #pragma unroll
                for (int mf = 0; mf < 2; mf++)
                    #pragma unroll
                    for (int j = 0; j < 2; j++) {
                        int nf = nh * 2 + j;
                        mma16816(acc[mf][nf], ah[mf], bh[j]);
                        mma16816(acc[mf][nf], ah[mf], bl[j]);
                        mma16816(acc[mf][nf], al[mf], bh[j]);
                    }
            }
        }
        __syncthreads();
    }

    // epilogue: + b2' + feats residual, fp32 out
    int g = lane >> 2, q = lane & 3;
    #pragma unroll
    for (int mf = 0; mf < 2; mf++) {
        #pragma unroll
        for (int nf = 0; nf < 4; nf++) {
            int col = wn * 32 + nf * 8 + q * 2;
            float b0 = g_b2p[col], b1v = g_b2p[col + 1];
            #pragma unroll
            for (int half = 0; half < 2; half++) {
                int m = m0 + wm * 32 + mf * 16 + g + half * 8;
                if (m < n) {
                    size_t o = (size_t)m * DIMC + col;
                    float2 fr = *(const float2*)(feats + o);
                    float2 ov;
                    ov.x = acc[mf][nf][half*2+0] + b0  + fr.x;
                    ov.y = acc[mf][nf][half*2+1] + b1v + fr.y;
                    *(float2*)(out + o) = ov;
                }
            }
        }
    }
}

// ---------------------------------------------------------------------------
extern "C" void kernel_launch(void* const* d_in, const int* in_sizes, int n_in,
                              void* d_out, int out_size)
{
    const float* feats = (const float*)d_in[0];
    const int*   nbr   = (const int*)  d_in[1];
    const float* dw_w  = (const float*)d_in[2];
    const float* dw_b  = (const float*)d_in[3];
    const float* ln_g  = (const float*)d_in[4];
    const float* ln_b  = (const float*)d_in[5];
    const float* w1    = (const float*)d_in[6];
    const float* b1    = (const float*)d_in[7];
    const float* grn_g = (const float*)d_in[8];
    const float* grn_b = (const float*)d_in[9];
    const float* w2    = (const float*)d_in[10];
    const float* b2    = (const float*)d_in[11];
    float* out = (float*)d_out;

    int n = in_sizes[0] / DIMC;

    const int SMEM1 = 192 * 1024;
    const int SMEM2 = 128 * 1024;
    cudaFuncSetAttribute(gemm1_tc, cudaFuncAttributeMaxDynamicSharedMemorySize, SMEM1);
    cudaFuncSetAttribute(gemm2_tc, cudaFuncAttributeMaxDynamicSharedMemorySize, SMEM2);

    zero_ssq_k<<<1, HID>>>();

    int blocks_a = (n * 32 + 255) / 256;
    dwconv_ln_k<<<blocks_a, 256>>>(feats, nbr, dw_w, dw_b, ln_g, ln_b, n);

    w1t_prep_k<<<(HID * DIMC + 255) / 256, 256>>>(w1);

    int mtiles = (n + 127) / 128;
    dim3 g1(mtiles, HID / 256);
    gemm1_tc<<<g1, 512, SMEM1>>>(b1, n);

    grn_scale_k<<<1, HID>>>(grn_g);
    build_w2t_k<<<(DIMC * HID + 255) / 256, 256>>>(w2);
    build_b2p_k<<<1, DIMC>>>(grn_b, w2, b2);

    gemm2_tc<<<mtiles, 512, SMEM2>>>(feats, out, n);
}

// round 7
// speedup vs baseline: 2.3853x; 1.4242x over previous
#include <cuda_runtime.h>
#include <cuda_fp16.h>
#include <math.h>
#include <stdint.h>

// Problem constants (fixed by the dataset)
#define NMAX   100000
#define DIMC   128
#define HID    512
#define KTAPS  343

// ---------------- scratch (device globals; no allocation allowed) ----------
__device__ __half g_x1[(size_t)NMAX * DIMC];    // post dwconv+LN (fp16, 25.6 MB)
__device__ __half g_w1t[HID * DIMC];            // w1^T [n][k]
__device__ __half g_h[(size_t)NMAX * HID];      // gelu(h) fp16 (102.4 MB)
__device__ float  g_ssq[HID];
__device__ float  g_s  [HID];                   // GRN scale: grn_g*nx + 1
__device__ __half g_w2t[DIMC * HID];            // (diag(s) w2)^T [n][k]
__device__ float  g_b2p[DIMC];                  // grn_b @ w2 + b2

// ======================= helpers ===========================================
__device__ __forceinline__ uint32_t smem_u32(const void* p) {
    uint32_t a;
    asm("{ .reg .u64 t; cvta.to.shared.u64 t, %1; cvt.u32.u64 %0, t; }" : "=r"(a) : "l"(p));
    return a;
}
__device__ __forceinline__ float gelu_exact(float v) {
    return 0.5f * v * (1.0f + erff(v * 0.70710678118654752f));
}
// swizzled byte offset within a [rows][64 fp16] (128B/row) smem tile
__device__ __forceinline__ uint32_t sw_off(int row, int u) {   // u = 16B unit 0..7
    return (uint32_t)((row * 128 + u * 16) ^ ((row & 7) << 4));
}
__device__ __forceinline__ void ldsm4(uint32_t* r, uint32_t addr) {
    asm volatile("ldmatrix.sync.aligned.m8n8.x4.shared.b16 {%0,%1,%2,%3}, [%4];"
        : "=r"(r[0]), "=r"(r[1]), "=r"(r[2]), "=r"(r[3]) : "r"(addr));
}
__device__ __forceinline__ void mma16816(float* c, const uint32_t* a, const uint32_t* b) {
    asm volatile("mma.sync.aligned.m16n8k16.row.col.f32.f16.f16.f32 "
        "{%0,%1,%2,%3}, {%4,%5,%6,%7}, {%8,%9}, {%0,%1,%2,%3};"
        : "+f"(c[0]), "+f"(c[1]), "+f"(c[2]), "+f"(c[3])
        : "r"(a[0]), "r"(a[1]), "r"(a[2]), "r"(a[3]), "r"(b[0]), "r"(b[1]));
}
__device__ __forceinline__ void cp16(uint32_t dst, const void* src, bool pred) {
    int sz = pred ? 16 : 0;
    asm volatile("cp.async.cg.shared.global [%0], [%1], 16, %2;"
        :: "r"(dst), "l"(src), "r"(sz));
}
#define CP_COMMIT() asm volatile("cp.async.commit_group;" ::: "memory")
#define CP_WAIT(N)  asm volatile("cp.async.wait_group %0;" :: "n"(N) : "memory")

// ---------------------------------------------------------------------------
__global__ void zero_ssq_k() { g_ssq[threadIdx.x] = 0.f; }

// ---------------- Kernel A: sparse depthwise conv + LayerNorm -> fp16 ------
__global__ __launch_bounds__(256) void dwconv_ln_k(
    const float* __restrict__ feats, const int* __restrict__ nbr,
    const float* __restrict__ dw_w, const float* __restrict__ dw_b,
    const float* __restrict__ ln_g, const float* __restrict__ ln_b, int n)
{
    int site = (blockIdx.x * blockDim.x + threadIdx.x) >> 5;
    int lane = threadIdx.x & 31;
    if (site >= n) return;

    const int* row = nbr + (size_t)site * KTAPS;
    float4 acc = make_float4(0.f, 0.f, 0.f, 0.f);

    for (int k0 = 0; k0 < KTAPS; k0 += 32) {
        int k   = k0 + lane;
        int idx = (k < KTAPS) ? row[k] : n;
        unsigned valid = __ballot_sync(0xffffffffu, idx < n);
        while (valid) {
            int b = __ffs(valid) - 1;
            valid &= valid - 1;
            int j  = __shfl_sync(0xffffffffu, idx, b);
            int kk = k0 + b;
            float4 f = *(const float4*)(feats + (size_t)j * DIMC + lane * 4);
            float4 w = *(const float4*)(dw_w + kk * DIMC + lane * 4);
            acc.x = fmaf(f.x, w.x, acc.x);
            acc.y = fmaf(f.y, w.y, acc.y);
            acc.z = fmaf(f.z, w.z, acc.z);
            acc.w = fmaf(f.w, w.w, acc.w);
        }
    }
    float4 bb = *(const float4*)(dw_b + lane * 4);
    acc.x += bb.x; acc.y += bb.y; acc.z += bb.z; acc.w += bb.w;

    float s1 = acc.x + acc.y + acc.z + acc.w;
    float s2 = acc.x*acc.x + acc.y*acc.y + acc.z*acc.z + acc.w*acc.w;
    #pragma unroll
    for (int o = 16; o; o >>= 1) {
        s1 += __shfl_xor_sync(0xffffffffu, s1, o);
        s2 += __shfl_xor_sync(0xffffffffu, s2, o);
    }
    float mean = s1 * (1.f / DIMC);
    float var  = s2 * (1.f / DIMC) - mean * mean;
    float rstd = rsqrtf(var + 1e-6f);

    float4 g = *(const float4*)(ln_g + lane * 4);
    float4 b = *(const float4*)(ln_b + lane * 4);
    float v0 = (acc.x - mean) * rstd * g.x + b.x;
    float v1 = (acc.y - mean) * rstd * g.y + b.y;
    float v2 = (acc.z - mean) * rstd * g.z + b.z;
    float v3 = (acc.w - mean) * rstd * g.w + b.w;

    size_t o = (size_t)site * DIMC + lane * 4;
    *(half2*)(g_x1 + o)     = __floats2half2_rn(v0, v1);
    *(half2*)(g_x1 + o + 2) = __floats2half2_rn(v2, v3);
}

// ---------------- prep: w1t[n][k] = fp16(w1[k][n]) -------------------------
__global__ void w1t_prep_k(const float* __restrict__ w1)
{
    int idx = blockIdx.x * blockDim.x + threadIdx.x;   // 65536 = 512*128
    if (idx < HID * DIMC) {
        int nrow = idx >> 7, k = idx & 127;
        g_w1t[idx] = __float2half_rn(w1[(size_t)k * HID + nrow]);
    }
}

// ============== async chunk loader =========================================
// Loads one K-chunk (64 cols fp16 = 128B/row) of A (128 rows, zero-padded
// past n_valid) and B (brows rows) into a swizzled smem stage. One group.
__device__ __forceinline__ void load_chunk_async(
    uint32_t sA, uint32_t sB,
    const __half* __restrict__ A, int a_stride,
    const __half* __restrict__ B, int b_stride, int brows,
    int m0, int n_valid, int nb0, int kc, int tid)
{
    // A: 128 rows x 8 units = 1024 cp16 -> 2 per thread
    #pragma unroll
    for (int i = 0; i < 2; i++) {
        int idx = tid + i * 512;
        int row = idx >> 3, u = idx & 7;
        bool ok = (m0 + row < n_valid);
        size_t go = (size_t)(m0 + row) * a_stride + kc * 64 + u * 8;
        cp16(sA + sw_off(row, u), A + go, ok);
    }
    // B: brows x 8 units
    for (int idx = tid; idx < brows * 8; idx += 512) {
        int row = idx >> 3, u = idx & 7;
        size_t go = (size_t)(nb0 + row) * b_stride + kc * 64 + u * 8;
        cp16(sB + sw_off(row, u), B + go, true);
    }
    CP_COMMIT();
}

// ---------------- Kernel B: GEMM1  h = gelu(x1 @ w1 + b1), + ssq -----------
// Block 128M x 256N, K=128 (2 chunks of 64), 512 thr = 16 warps (4m x 4n),
// warp tile 32x64. smem: 2 stages x (A 16KB + B 32KB) = 96KB.
__global__ __launch_bounds__(512) void gemm1_tc(const float* __restrict__ b1, int n)
{
    extern __shared__ char smem[];
    const int STG = 49152;
    __shared__ float scs[256];

    int tid = threadIdx.x;
    int wid = tid >> 5, lane = tid & 31;
    int wm = wid >> 2, wn = wid & 3;
    int lr = lane & 15, lh = lane >> 4;
    int m0 = blockIdx.x * 128;
    int n0 = blockIdx.y * 256;

    if (tid < 256) scs[tid] = 0.f;

    uint32_t base = smem_u32(smem);
    // stage s: A = base + s*STG, B = +16384 (32KB)

    float acc[2][8][4];
    #pragma unroll
    for (int mf = 0; mf < 2; mf++)
        #pragma unroll
        for (int nf = 0; nf < 8; nf++)
            #pragma unroll
            for (int r = 0; r < 4; r++) acc[mf][nf][r] = 0.f;

    // issue both chunks' loads up front
    #pragma unroll
    for (int kc = 0; kc < 2; kc++) {
        uint32_t sb = base + kc * STG;
        load_chunk_async(sb, sb + 16384,
                         g_x1, DIMC, g_w1t, DIMC, 256,
                         m0, n, n0, kc, tid);
    }

    #pragma unroll
    for (int kc = 0; kc < 2; kc++) {
        if (kc == 0) { CP_WAIT(1); } else { CP_WAIT(0); }
        __syncthreads();
        uint32_t uA = base + kc * STG, uB = uA + 16384;
        #pragma unroll
        for (int ks = 0; ks < 4; ks++) {
            int u = ks * 2 + lh;
            uint32_t ah[2][4];
            #pragma unroll
            for (int mf = 0; mf < 2; mf++) {
                int row = wm * 32 + mf * 16 + lr;
                ldsm4(ah[mf], uA + sw_off(row, u));
            }
            #pragma unroll
            for (int nh = 0; nh < 4; nh++) {
                int row = wn * 64 + nh * 16 + lr;
                uint32_t t[4], bf[2][2];
                ldsm4(t, uB + sw_off(row, u));
                bf[0][0] = t[0]; bf[0][1] = t[2];
                bf[1][0] = t[1]; bf[1][1] = t[3];
                #pragma unroll
                for (int mf = 0; mf < 2; mf++)
                    #pragma unroll
                    for (int j = 0; j < 2; j++)
                        mma16816(acc[mf][nh * 2 + j], ah[mf], bf[j]);
            }
        }
        __syncthreads();
    }

    // epilogue: bias + GELU, fp16 store, per-column ssq (fp32, unrounded)
    int g = lane >> 2, q = lane & 3;
    float csq[16];
    #pragma unroll
    for (int i = 0; i < 16; i++) csq[i] = 0.f;
    #pragma unroll
    for (int mf = 0; mf < 2; mf++) {
        #pragma unroll
        for (int nf = 0; nf < 8; nf++) {
            int col = n0 + wn * 64 + nf * 8 + q * 2;
            float bia0 = b1[col], bia1 = b1[col + 1];
            #pragma unroll
            for (int half_i = 0; half_i < 2; half_i++) {
                int m = m0 + wm * 32 + mf * 16 + g + half_i * 8;
                if (m < n) {
                    float v0 = gelu_exact(acc[mf][nf][half_i*2+0] + bia0);
                    float v1 = gelu_exact(acc[mf][nf][half_i*2+1] + bia1);
                    *(half2*)(g_h + (size_t)m * HID + col) = __floats2half2_rn(v0, v1);
                    csq[nf*2+0] += v0 * v0;
                    csq[nf*2+1] += v1 * v1;
                }
            }
        }
    }
    __syncthreads();
    #pragma unroll
    for (int nf = 0; nf < 8; nf++) {
        atomicAdd(&scs[wn * 64 + nf * 8 + q * 2],     csq[nf*2+0]);
        atomicAdd(&scs[wn * 64 + nf * 8 + q * 2 + 1], csq[nf*2+1]);
    }
    __syncthreads();
    if (tid < 256) atomicAdd(&g_ssq[n0 + tid], scs[tid]);
}

// ---------------- Kernel D1: GRN channel scale -----------------------------
__global__ void grn_scale_k(const float* __restrict__ grn_g)
{
    int c = threadIdx.x;            // 512 threads, 1 block
    float gx = sqrtf(g_ssq[c]);
    __shared__ float red[16];
    __shared__ float mean_s;
    float v = gx;
    #pragma unroll
    for (int o = 16; o; o >>= 1) v += __shfl_xor_sync(0xffffffffu, v, o);
    if ((c & 31) == 0) red[c >> 5] = v;
    __syncthreads();
    if (c < 16) {
        float w = red[c];
        #pragma unroll
        for (int o = 8; o; o >>= 1) w += __shfl_xor_sync(0xffffu, w, o);
        if (c == 0) mean_s = w * (1.f / HID);
    }
    __syncthreads();
    float nx = gx / (mean_s + 1e-6f);
    g_s[c] = grn_g[c] * nx + 1.0f;
}

// ---------------- Kernel D2: w2t[n][k] = fp16(s[k]*w2[k][n]) ---------------
__global__ void build_w2t_k(const float* __restrict__ w2)
{
    int idx = blockIdx.x * blockDim.x + threadIdx.x;   // 65536 = 128*512
    if (idx < DIMC * HID) {
        int nrow = idx >> 9, k = idx & 511;
        g_w2t[idx] = __float2half_rn(g_s[k] * w2[(size_t)k * DIMC + nrow]);
    }
}

// ---------------- Kernel D3: b2' = grn_b @ w2 + b2 -------------------------
__global__ void build_b2p_k(const float* __restrict__ grn_b,
                            const float* __restrict__ w2,
                            const float* __restrict__ b2)
{
    int c = threadIdx.x;            // 128 threads
    float acc = 0.f;
    for (int k = 0; k < HID; k++) acc = fmaf(grn_b[k], w2[(size_t)k * DIMC + c], acc);
    g_b2p[c] = b2[c] + acc;
}

// ---------------- Kernel E: GEMM2  out = h @ w2' + b2' + feats -------------
// Block 128M x 128N, K=512 (8 chunks, 2-stage ring), 512 thr, warp 32x32.
// smem: 2 stages x (A 16KB + B 16KB) = 64KB.
__global__ __launch_bounds__(512) void gemm2_tc(
    const float* __restrict__ feats, float* __restrict__ out, int n)
{
    extern __shared__ char smem[];
    const int STG = 32768;

    int tid = threadIdx.x;
    int wid = tid >> 5, lane = tid & 31;
    int wm = wid >> 2, wn = wid & 3;
    int lr = lane & 15, lh = lane >> 4;
    int m0 = blockIdx.x * 128;

    uint32_t base = smem_u32(smem);
    // stage s: A = base + s*STG, B = +16384

    float acc[2][4][4];
    #pragma unroll
    for (int mf = 0; mf < 2; mf++)
        #pragma unroll
        for (int nf = 0; nf < 4; nf++)
            #pragma unroll
            for (int r = 0; r < 4; r++) acc[mf][nf][r] = 0.f;

    load_chunk_async(base, base + 16384,
                     g_h, HID, g_w2t, HID, 128,
                     m0, n, 0, 0, tid);

    for (int kc = 0; kc < 8; kc++) {
        if (kc < 7) {
            uint32_t sb = base + ((kc + 1) & 1) * STG;
            load_chunk_async(sb, sb + 16384,
                             g_h, HID, g_w2t, HID, 128,
                             m0, n, 0, kc + 1, tid);
            CP_WAIT(1);
        } else {
            CP_WAIT(0);
        }
        __syncthreads();

        uint32_t uA = base + (kc & 1) * STG, uB = uA + 16384;
        #pragma unroll
        for (int ks = 0; ks < 4; ks++) {
            int u = ks * 2 + lh;
            uint32_t ah[2][4];
            #pragma unroll
            for (int mf = 0; mf < 2; mf++) {
                int row = wm * 32 + mf * 16 + lr;
                ldsm4(ah[mf], uA + sw_off(row, u));
            }
            #pragma unroll
            for (int nh = 0; nh < 2; nh++) {
                int row = wn * 32 + nh * 16 + lr;
                uint32_t t[4], bf[2][2];
                ldsm4(t, uB + sw_off(row, u));
                bf[0][0] = t[0]; bf[0][1] = t[2];
                bf[1][0] = t[1]; bf[1][1] = t[3];
                #pragma unroll
                for (int mf = 0; mf < 2; mf++)
                    #pragma unroll
                    for (int j = 0; j < 2; j++)
                        mma16816(acc[mf][nh * 2 + j], ah[mf], bf[j]);
            }
        }
        __syncthreads();
    }

    // epilogue: + b2' + feats residual, fp32 out
    int g = lane >> 2, q = lane & 3;
    #pragma unroll
    for (int mf = 0; mf < 2; mf++) {
        #pragma unroll
        for (int nf = 0; nf < 4; nf++) {
            int col = wn * 32 + nf * 8 + q * 2;
            float b0 = g_b2p[col], b1v = g_b2p[col + 1];
            #pragma unroll
            for (int half_i = 0; half_i < 2; half_i++) {
                int m = m0 + wm * 32 + mf * 16 + g + half_i * 8;
                if (m < n) {
                    size_t o = (size_t)m * DIMC + col;
                    float2 fr = *(const float2*)(feats + o);
                    float2 ov;
                    ov.x = acc[mf][nf][half_i*2+0] + b0  + fr.x;
                    ov.y = acc[mf][nf][half_i*2+1] + b1v + fr.y;
                    *(float2*)(out + o) = ov;
                }
            }
        }
    }
}

// ---------------------------------------------------------------------------
extern "C" void kernel_launch(void* const* d_in, const int* in_sizes, int n_in,
                              void* d_out, int out_size)
{
    const float* feats = (const float*)d_in[0];
    const int*   nbr   = (const int*)  d_in[1];
    const float* dw_w  = (const float*)d_in[2];
    const float* dw_b  = (const float*)d_in[3];
    const float* ln_g  = (const float*)d_in[4];
    const float* ln_b  = (const float*)d_in[5];
    const float* w1    = (const float*)d_in[6];
    const float* b1    = (const float*)d_in[7];
    const float* grn_g = (const float*)d_in[8];
    const float* grn_b = (const float*)d_in[9];
    const float* w2    = (const float*)d_in[10];
    const float* b2    = (const float*)d_in[11];
    float* out = (float*)d_out;

    int n = in_sizes[0] / DIMC;

    const int SMEM1 = 96 * 1024;
    const int SMEM2 = 64 * 1024;
    cudaFuncSetAttribute(gemm1_tc, cudaFuncAttributeMaxDynamicSharedMemorySize, SMEM1);
    cudaFuncSetAttribute(gemm2_tc, cudaFuncAttributeMaxDynamicSharedMemorySize, SMEM2);

    zero_ssq_k<<<1, HID>>>();

    int blocks_a = (n * 32 + 255) / 256;
    dwconv_ln_k<<<blocks_a, 256>>>(feats, nbr, dw_w, dw_b, ln_g, ln_b, n);

    w1t_prep_k<<<(HID * DIMC + 255) / 256, 256>>>(w1);

    int mtiles = (n + 127) / 128;
    dim3 g1(mtiles, HID / 256);
    gemm1_tc<<<g1, 512, SMEM1>>>(b1, n);

    grn_scale_k<<<1, HID>>>(grn_g);
    build_w2t_k<<<(DIMC * HID + 255) / 256, 256>>>(w2);
    build_b2p_k<<<1, DIMC>>>(grn_b, w2, b2);

    gemm2_tc<<<mtiles, 512, SMEM2>>>(feats, out, n);
}

// round 8
// speedup vs baseline: 2.8474x; 1.1938x over previous
#include <cuda_runtime.h>
#include <cuda_fp16.h>
#include <math.h>
#include <stdint.h>

// Problem constants (fixed by the dataset)
#define NMAX   100000
#define DIMC   128
#define HID    512
#define KTAPS  343

// ---------------- scratch (device globals; no allocation allowed) ----------
__device__ __half g_x1[(size_t)NMAX * DIMC];    // post dwconv+LN (fp16, 25.6 MB)
__device__ __half g_w1t[HID * DIMC];            // w1^T [n][k]
__device__ __half g_h[(size_t)NMAX * HID];      // gelu(h) fp16 (102.4 MB)
__device__ float  g_ssq[HID];
__device__ float  g_s  [HID];                   // GRN scale: grn_g*nx + 1
__device__ __half g_w2t[DIMC * HID];            // (diag(s) w2)^T [n][k]
__device__ float  g_b2p[DIMC];                  // grn_b @ w2 + b2

// ======================= helpers ===========================================
__device__ __forceinline__ uint32_t smem_u32(const void* p) {
    uint32_t a;
    asm("{ .reg .u64 t; cvta.to.shared.u64 t, %1; cvt.u32.u64 %0, t; }" : "=r"(a) : "l"(p));
    return a;
}
__device__ __forceinline__ float gelu_exact(float v) {
    return 0.5f * v * (1.0f + erff(v * 0.70710678118654752f));
}
// swizzled byte offset within a [rows][64 fp16] (128B/row) smem tile
__device__ __forceinline__ uint32_t sw_off(int row, int u) {   // u = 16B unit 0..7
    return (uint32_t)((row * 128 + u * 16) ^ ((row & 7) << 4));
}
__device__ __forceinline__ void ldsm4(uint32_t* r, uint32_t addr) {
    asm volatile("ldmatrix.sync.aligned.m8n8.x4.shared.b16 {%0,%1,%2,%3}, [%4];"
        : "=r"(r[0]), "=r"(r[1]), "=r"(r[2]), "=r"(r[3]) : "r"(addr));
}
__device__ __forceinline__ void mma16816(float* c, const uint32_t* a, const uint32_t* b) {
    asm volatile("mma.sync.aligned.m16n8k16.row.col.f32.f16.f16.f32 "
        "{%0,%1,%2,%3}, {%4,%5,%6,%7}, {%8,%9}, {%0,%1,%2,%3};"
        : "+f"(c[0]), "+f"(c[1]), "+f"(c[2]), "+f"(c[3])
        : "r"(a[0]), "r"(a[1]), "r"(a[2]), "r"(a[3]), "r"(b[0]), "r"(b[1]));
}
__device__ __forceinline__ void cp16(uint32_t dst, const void* src, bool pred) {
    int sz = pred ? 16 : 0;
    asm volatile("cp.async.cg.shared.global [%0], [%1], 16, %2;"
        :: "r"(dst), "l"(src), "r"(sz));
}
#define CP_COMMIT() asm volatile("cp.async.commit_group;" ::: "memory")
#define CP_WAIT(N)  asm volatile("cp.async.wait_group %0;" :: "n"(N) : "memory")

// ---------------- Kernel A: sparse depthwise conv + LayerNorm -> fp16 ------
__global__ __launch_bounds__(256) void dwconv_ln_k(
    const float* __restrict__ feats, const int* __restrict__ nbr,
    const float* __restrict__ dw_w, const float* __restrict__ dw_b,
    const float* __restrict__ ln_g, const float* __restrict__ ln_b, int n)
{
    int site = (blockIdx.x * blockDim.x + threadIdx.x) >> 5;
    int lane = threadIdx.x & 31;
    if (site >= n) return;

    const int* row = nbr + (size_t)site * KTAPS;
    float4 acc = make_float4(0.f, 0.f, 0.f, 0.f);

    for (int k0 = 0; k0 < KTAPS; k0 += 32) {
        int k   = k0 + lane;
        int idx = (k < KTAPS) ? row[k] : n;
        unsigned valid = __ballot_sync(0xffffffffu, idx < n);
        while (valid) {
            int b = __ffs(valid) - 1;
            valid &= valid - 1;
            int j  = __shfl_sync(0xffffffffu, idx, b);
            int kk = k0 + b;
            float4 f = *(const float4*)(feats + (size_t)j * DIMC + lane * 4);
            float4 w = *(const float4*)(dw_w + kk * DIMC + lane * 4);
            acc.x = fmaf(f.x, w.x, acc.x);
            acc.y = fmaf(f.y, w.y, acc.y);
            acc.z = fmaf(f.z, w.z, acc.z);
            acc.w = fmaf(f.w, w.w, acc.w);
        }
    }
    float4 bb = *(const float4*)(dw_b + lane * 4);
    acc.x += bb.x; acc.y += bb.y; acc.z += bb.z; acc.w += bb.w;

    float s1 = acc.x + acc.y + acc.z + acc.w;
    float s2 = acc.x*acc.x + acc.y*acc.y + acc.z*acc.z + acc.w*acc.w;
    #pragma unroll
    for (int o = 16; o; o >>= 1) {
        s1 += __shfl_xor_sync(0xffffffffu, s1, o);
        s2 += __shfl_xor_sync(0xffffffffu, s2, o);
    }
    float mean = s1 * (1.f / DIMC);
    float var  = s2 * (1.f / DIMC) - mean * mean;
    float rstd = rsqrtf(var + 1e-6f);

    float4 g = *(const float4*)(ln_g + lane * 4);
    float4 b = *(const float4*)(ln_b + lane * 4);
    float v0 = (acc.x - mean) * rstd * g.x + b.x;
    float v1 = (acc.y - mean) * rstd * g.y + b.y;
    float v2 = (acc.z - mean) * rstd * g.z + b.z;
    float v3 = (acc.w - mean) * rstd * g.w + b.w;

    size_t o = (size_t)site * DIMC + lane * 4;
    *(half2*)(g_x1 + o)     = __floats2half2_rn(v0, v1);
    *(half2*)(g_x1 + o + 2) = __floats2half2_rn(v2, v3);
}

// ---------------- prep: w1t[n][k] = fp16(w1[k][n]); also zero ssq ----------
__global__ void w1t_prep_k(const float* __restrict__ w1)
{
    int idx = blockIdx.x * blockDim.x + threadIdx.x;   // 65536 = 512*128
    if (idx < HID) g_ssq[idx] = 0.f;
    if (idx < HID * DIMC) {
        int nrow = idx >> 7, k = idx & 127;
        g_w1t[idx] = __float2half_rn(w1[(size_t)k * HID + nrow]);
    }
}

// ============== async chunk loader =========================================
// Loads one K-chunk (64 cols fp16 = 128B/row) of A (128 rows, zero-padded
// past n_valid) and B (128 rows) into a swizzled smem stage. One group.
__device__ __forceinline__ void load_chunk_async(
    uint32_t sA, uint32_t sB,
    const __half* __restrict__ A, int a_stride,
    const __half* __restrict__ B, int b_stride,
    int m0, int n_valid, int nb0, int kc, int tid)
{
    // A: 128 rows x 8 units = 1024 cp16 -> 2 per thread
    #pragma unroll
    for (int i = 0; i < 2; i++) {
        int idx = tid + i * 512;
        int row = idx >> 3, u = idx & 7;
        bool ok = (m0 + row < n_valid);
        size_t go = (size_t)(m0 + row) * a_stride + kc * 64 + u * 8;
        cp16(sA + sw_off(row, u), A + go, ok);
    }
    // B: 128 rows x 8 units
    #pragma unroll
    for (int i = 0; i < 2; i++) {
        int idx = tid + i * 512;
        int row = idx >> 3, u = idx & 7;
        size_t go = (size_t)(nb0 + row) * b_stride + kc * 64 + u * 8;
        cp16(sB + sw_off(row, u), B + go, true);
    }
    CP_COMMIT();
}

// ---------------- Kernel B: GEMM1  h = gelu(x1 @ w1 + b1), + ssq -----------
// Block 128M x 128N, K=128 (2 chunks of 64), 512 thr = 16 warps (4m x 4n),
// warp tile 32x32. smem: 2 stages x (A 16KB + B 16KB) = 64KB. 2 CTAs/SM.
__global__ __launch_bounds__(512, 2) void gemm1_tc(const float* __restrict__ b1, int n)
{
    extern __shared__ char smem[];
    const int STG = 32768;
    __shared__ float scs[128];

    int tid = threadIdx.x;
    int wid = tid >> 5, lane = tid & 31;
    int wm = wid >> 2, wn = wid & 3;
    int lr = lane & 15, lh = lane >> 4;
    int m0 = blockIdx.x * 128;
    int n0 = blockIdx.y * 128;

    if (tid < 128) scs[tid] = 0.f;

    uint32_t base = smem_u32(smem);
    // hoisted ldsm row bases (swizzle xor folded per-u below)
    uint32_t arow0 = (uint32_t)((wm * 32 + lr) * 128);
    uint32_t brow0 = (uint32_t)((wn * 32 + lr) * 128);
    uint32_t sx    = (uint32_t)((lr & 7) << 4);

    float acc[2][4][4];
    #pragma unroll
    for (int mf = 0; mf < 2; mf++)
        #pragma unroll
        for (int nf = 0; nf < 4; nf++)
            #pragma unroll
            for (int r = 0; r < 4; r++) acc[mf][nf][r] = 0.f;

    // issue both chunks' loads up front
    #pragma unroll
    for (int kc = 0; kc < 2; kc++) {
        uint32_t sb = base + kc * STG;
        load_chunk_async(sb, sb + 16384,
                         g_x1, DIMC, g_w1t, DIMC,
                         m0, n, n0, kc, tid);
    }

    #pragma unroll
    for (int kc = 0; kc < 2; kc++) {
        if (kc == 0) { CP_WAIT(1); } else { CP_WAIT(0); }
        __syncthreads();
        uint32_t uA = base + kc * STG, uB = uA + 16384;
        #pragma unroll
        for (int ks = 0; ks < 4; ks++) {
            uint32_t xu = (uint32_t)(((ks * 2 + lh) << 4)) ^ sx;
            uint32_t ah[2][4];
            #pragma unroll
            for (int mf = 0; mf < 2; mf++)
                ldsm4(ah[mf], uA + arow0 + mf * 2048 + xu);
            #pragma unroll
            for (int nh = 0; nh < 2; nh++) {
                uint32_t t[4], bf[2][2];
                ldsm4(t, uB + brow0 + nh * 2048 + xu);
                bf[0][0] = t[0]; bf[0][1] = t[2];
                bf[1][0] = t[1]; bf[1][1] = t[3];
                #pragma unroll
                for (int mf = 0; mf < 2; mf++)
                    #pragma unroll
                    for (int j = 0; j < 2; j++)
                        mma16816(acc[mf][nh * 2 + j], ah[mf], bf[j]);
            }
        }
        __syncthreads();
    }

    // epilogue: bias + GELU, fp16 store, per-column ssq (fp32, unrounded)
    int g = lane >> 2, q = lane & 3;
    float csq[8];
    #pragma unroll
    for (int i = 0; i < 8; i++) csq[i] = 0.f;
    #pragma unroll
    for (int mf = 0; mf < 2; mf++) {
        #pragma unroll
        for (int nf = 0; nf < 4; nf++) {
            int col = n0 + wn * 32 + nf * 8 + q * 2;
            float bia0 = b1[col], bia1 = b1[col + 1];
            #pragma unroll
            for (int half_i = 0; half_i < 2; half_i++) {
                int m = m0 + wm * 32 + mf * 16 + g + half_i * 8;
                if (m < n) {
                    float v0 = gelu_exact(acc[mf][nf][half_i*2+0] + bia0);
                    float v1 = gelu_exact(acc[mf][nf][half_i*2+1] + bia1);
                    *(half2*)(g_h + (size_t)m * HID + col) = __floats2half2_rn(v0, v1);
                    csq[nf*2+0] += v0 * v0;
                    csq[nf*2+1] += v1 * v1;
                }
            }
        }
    }
    __syncthreads();
    #pragma unroll
    for (int nf = 0; nf < 4; nf++) {
        atomicAdd(&scs[wn * 32 + nf * 8 + q * 2],     csq[nf*2+0]);
        atomicAdd(&scs[wn * 32 + nf * 8 + q * 2 + 1], csq[nf*2+1]);
    }
    __syncthreads();
    if (tid < 128) atomicAdd(&g_ssq[n0 + tid], scs[tid]);
}

// ---------------- Kernel D1: GRN channel scale -----------------------------
__global__ void grn_scale_k(const float* __restrict__ grn_g)
{
    int c = threadIdx.x;            // 512 threads, 1 block
    float gx = sqrtf(g_ssq[c]);
    __shared__ float red[16];
    __shared__ float mean_s;
    float v = gx;
    #pragma unroll
    for (int o = 16; o; o >>= 1) v += __shfl_xor_sync(0xffffffffu, v, o);
    if ((c & 31) == 0) red[c >> 5] = v;
    __syncthreads();
    if (c < 16) {
        float w = red[c];
        #pragma unroll
        for (int o = 8; o; o >>= 1) w += __shfl_xor_sync(0xffffu, w, o);
        if (c == 0) mean_s = w * (1.f / HID);
    }
    __syncthreads();
    float nx = gx / (mean_s + 1e-6f);
    g_s[c] = grn_g[c] * nx + 1.0f;
}

// ---------------- Kernel D2: w2t[n][k] = fp16(s[k]*w2[k][n]) ---------------
__global__ void build_w2t_k(const float* __restrict__ w2)
{
    int idx = blockIdx.x * blockDim.x + threadIdx.x;   // 65536 = 128*512
    if (idx < DIMC * HID) {
        int nrow = idx >> 9, k = idx & 511;
        g_w2t[idx] = __float2half_rn(g_s[k] * w2[(size_t)k * DIMC + nrow]);
    }
}

// ---------------- Kernel D3: b2' = grn_b @ w2 + b2 -------------------------
__global__ void build_b2p_k(const float* __restrict__ grn_b,
                            const float* __restrict__ w2,
                            const float* __restrict__ b2)
{
    int c = threadIdx.x;            // 128 threads
    float acc = 0.f;
    for (int k = 0; k < HID; k++) acc = fmaf(grn_b[k], w2[(size_t)k * DIMC + c], acc);
    g_b2p[c] = b2[c] + acc;
}

// ---------------- Kernel E: GEMM2  out = h @ w2' + b2' + feats -------------
// Block 128M x 128N, K=512 (8 chunks, 2-stage ring), 512 thr, warp 32x32.
// smem: 2 stages x (A 16KB + B 16KB) = 64KB. 2 CTAs/SM.
__global__ __launch_bounds__(512, 2) void gemm2_tc(
    const float* __restrict__ feats, float* __restrict__ out, int n)
{
    extern __shared__ char smem[];
    const int STG = 32768;

    int tid = threadIdx.x;
    int wid = tid >> 5, lane = tid & 31;
    int wm = wid >> 2, wn = wid & 3;
    int lr = lane & 15, lh = lane >> 4;
    int m0 = blockIdx.x * 128;

    uint32_t base = smem_u32(smem);
    uint32_t arow0 = (uint32_t)((wm * 32 + lr) * 128);
    uint32_t brow0 = (uint32_t)((wn * 32 + lr) * 128);
    uint32_t sx    = (uint32_t)((lr & 7) << 4);

    float acc[2][4][4];
    #pragma unroll
    for (int mf = 0; mf < 2; mf++)
        #pragma unroll
        for (int nf = 0; nf < 4; nf++)
            #pragma unroll
            for (int r = 0; r < 4; r++) acc[mf][nf][r] = 0.f;

    load_chunk_async(base, base + 16384,
                     g_h, HID, g_w2t, HID,
                     m0, n, 0, 0, tid);

    for (int kc = 0; kc < 8; kc++) {
        if (kc < 7) {
            uint32_t sb = base + ((kc + 1) & 1) * STG;
            load_chunk_async(sb, sb + 16384,
                             g_h, HID, g_w2t, HID,
                             m0, n, 0, kc + 1, tid);
            CP_WAIT(1);
        } else {
            CP_WAIT(0);
        }
        __syncthreads();

        uint32_t uA = base + (kc & 1) * STG, uB = uA + 16384;
        #pragma unroll
        for (int ks = 0; ks < 4; ks++) {
            uint32_t xu = (uint32_t)(((ks * 2 + lh) << 4)) ^ sx;
            uint32_t ah[2][4];
            #pragma unroll
            for (int mf = 0; mf < 2; mf++)
                ldsm4(ah[mf], uA + arow0 + mf * 2048 + xu);
            #pragma unroll
            for (int nh = 0; nh < 2; nh++) {
                uint32_t t[4], bf[2][2];
                ldsm4(t, uB + brow0 + nh * 2048 + xu);
                bf[0][0] = t[0]; bf[0][1] = t[2];
                bf[1][0] = t[1]; bf[1][1] = t[3];
                #pragma unroll
                for (int mf = 0; mf < 2; mf++)
                    #pragma unroll
                    for (int j = 0; j < 2; j++)
                        mma16816(acc[mf][nh * 2 + j], ah[mf], bf[j]);
            }
        }
        __syncthreads();
    }

    // epilogue: + b2' + feats residual, fp32 out
    int g = lane >> 2, q = lane & 3;
    #pragma unroll
    for (int mf = 0; mf < 2; mf++) {
        #pragma unroll
        for (int nf = 0; nf < 4; nf++) {
            int col = wn * 32 + nf * 8 + q * 2;
            float b0 = g_b2p[col], b1v = g_b2p[col + 1];
            #pragma unroll
            for (int half_i = 0; half_i < 2; half_i++) {
                int m = m0 + wm * 32 + mf * 16 + g + half_i * 8;
                if (m < n) {
                    size_t o = (size_t)m * DIMC + col;
                    float2 fr = *(const float2*)(feats + o);
                    float2 ov;
                    ov.x = acc[mf][nf][half_i*2+0] + b0  + fr.x;
                    ov.y = acc[mf][nf][half_i*2+1] + b1v + fr.y;
                    *(float2*)(out + o) = ov;
                }
            }
        }
    }
}

// ---------------------------------------------------------------------------
extern "C" void kernel_launch(void* const* d_in, const int* in_sizes, int n_in,
                              void* d_out, int out_size)
{
    const float* feats = (const float*)d_in[0];
    const int*   nbr   = (const int*)  d_in[1];
    const float* dw_w  = (const float*)d_in[2];
    const float* dw_b  = (const float*)d_in[3];
    const float* ln_g  = (const float*)d_in[4];
    const float* ln_b  = (const float*)d_in[5];
    const float* w1    = (const float*)d_in[6];
    const float* b1    = (const float*)d_in[7];
    const float* grn_g = (const float*)d_in[8];
    const float* grn_b = (const float*)d_in[9];
    const float* w2    = (const float*)d_in[10];
    const float* b2    = (const float*)d_in[11];
    float* out = (float*)d_out;

    int n = in_sizes[0] / DIMC;

    const int SMEM = 64 * 1024;
    cudaFuncSetAttribute(gemm1_tc, cudaFuncAttributeMaxDynamicSharedMemorySize, SMEM);
    cudaFuncSetAttribute(gemm2_tc, cudaFuncAttributeMaxDynamicSharedMemorySize, SMEM);

    int blocks_a = (n * 32 + 255) / 256;
    dwconv_ln_k<<<blocks_a, 256>>>(feats, nbr, dw_w, dw_b, ln_g, ln_b, n);

    w1t_prep_k<<<(HID * DIMC + 255) / 256, 256>>>(w1);

    int mtiles = (n + 127) / 128;
    dim3 g1(mtiles, DIMC / 128 * 4);   // (782, 4) -> N = 512 in 128-col tiles
    gemm1_tc<<<g1, 512, SMEM>>>(b1, n);

    grn_scale_k<<<1, HID>>>(grn_g);
    build_w2t_k<<<(DIMC * HID + 255) / 256, 256>>>(w2);
    build_b2p_k<<<1, DIMC>>>(grn_b, w2, b2);

    gemm2_tc<<<mtiles, 512, SMEM>>>(feats, out, n);
}